// round 11
// baseline (speedup 1.0000x reference)
#include <cuda_runtime.h>
#include <math.h>
#include <stdint.h>

// Problem constants (hardcoded from reference setup_inputs)
#define BATCH   2
#define FRAMES  16
#define SPATIAL 1024            // height*width = 32*32
#define HIDDEN  1024
#define NHEADS  16
#define HDIM    64
#define NTOK    (BATCH*FRAMES*SPATIAL)   // 32768
#define QKV_N   (3*HIDDEN)               // 3072
#define LN_EPS  1e-5f

// Scratch buffers (device globals; no runtime allocation allowed)
__device__ float g_xn[(size_t)NTOK * HIDDEN];        // 128 MB (tf32-rounded, K-permuted)
__device__ float g_qkv[(size_t)NTOK * QKV_N];        // 402 MB (natural layout)
__device__ float g_attn[(size_t)NTOK * HIDDEN];      // 128 MB (tf32-rounded, K-permuted)
__device__ float g_wqkv_r[(size_t)QKV_N * HIDDEN];   // 12 MB  (rounded+permuted)
__device__ float g_wout_r[(size_t)HIDDEN * HIDDEN];  // 4 MB   (rounded+permuted)

__device__ __forceinline__ float to_tf32(float x) {
    float r;
    asm("cvt.rna.tf32.f32 %0, %1;" : "=f"(r) : "f"(x));
    return r;
}

// K-dim permutation within each 8-column group: stored[2i]=orig[i], stored[2i+1]=orig[i+4]
__device__ __forceinline__ int kperm(int c) {
    const int i = c & 7;
    return (c & ~7) | ((i < 4) ? (2 * i) : (2 * (i - 4) + 1));
}

__device__ __forceinline__ void cp_async16(uint32_t saddr, const void* gaddr) {
    asm volatile("cp.async.cg.shared.global [%0], [%1], 16;" :: "r"(saddr), "l"(gaddr));
}

// ---------------------------------------------------------------------------
// Weight round+permute: out[row, kperm(c)] = tf32(w[row, c]), K = HIDDEN
// ---------------------------------------------------------------------------
__global__ void __launch_bounds__(256) round_perm_w(const float* __restrict__ w,
                                                    float* __restrict__ out)
{
    const int idx = blockIdx.x * 256 + threadIdx.x;
    const int c = idx & (HIDDEN - 1);
    out[(idx & ~(HIDDEN - 1)) | kperm(c)] = to_tf32(w[idx]);
}

// ---------------------------------------------------------------------------
// LayerNorm: one block per token; output tf32-rounded + K-permuted
// ---------------------------------------------------------------------------
__global__ void __launch_bounds__(256) ln_kernel(const float* __restrict__ x,
                                                 const float* __restrict__ gamma,
                                                 const float* __restrict__ beta)
{
    const int tok = blockIdx.x;
    const int tid = threadIdx.x;
    const float4* xr = reinterpret_cast<const float4*>(x + (size_t)tok * HIDDEN);
    float4 v = xr[tid];

    float s  = v.x + v.y + v.z + v.w;
    float ss = v.x*v.x + v.y*v.y + v.z*v.z + v.w*v.w;

    #pragma unroll
    for (int o = 16; o > 0; o >>= 1) {
        s  += __shfl_xor_sync(0xffffffffu, s,  o);
        ss += __shfl_xor_sync(0xffffffffu, ss, o);
    }
    __shared__ float red_s[8], red_ss[8];
    const int warp = tid >> 5, lane = tid & 31;
    if (lane == 0) { red_s[warp] = s; red_ss[warp] = ss; }
    __syncthreads();
    float fs = 0.f, fss = 0.f;
    #pragma unroll
    for (int i = 0; i < 8; i++) { fs += red_s[i]; fss += red_ss[i]; }

    const float mean = fs * (1.0f / HIDDEN);
    const float var  = fss * (1.0f / HIDDEN) - mean * mean;
    const float inv  = rsqrtf(var + LN_EPS);

    const float4 g = reinterpret_cast<const float4*>(gamma)[tid];
    const float4 b = reinterpret_cast<const float4*>(beta)[tid];
    // Thread covers orig cols 4*tid..4*tid+3 -> permuted positions within 8-group
    float* orow = g_xn + (size_t)tok * HIDDEN + ((4 * tid) & ~7) + (tid & 1);
    orow[0] = to_tf32((v.x - mean) * inv * g.x + b.x);
    orow[2] = to_tf32((v.y - mean) * inv * g.y + b.y);
    orow[4] = to_tf32((v.z - mean) * inv * g.z + b.z);
    orow[6] = to_tf32((v.w - mean) * inv * g.w + b.w);
}

// ---------------------------------------------------------------------------
// TF32 mma.sync GEMM (NT), K=1024 fixed: C[m][n] = sum_k A[m][k]*B[n][k]
// A, B pre-rounded to tf32 and K-permuted. CTA tile 256x128, BK=32,
// 256 threads = 8 warps (4Mx2N), warp tile 64x64. 3-stage cp.async pipeline.
// Canonical single-barrier order: wait_group -> __syncthreads -> fill -> compute.
// smem row stride LDT=40 -> conflict-free LDS.64 fragment loads.
// ---------------------------------------------------------------------------
#define GK      1024
#define BK      32
#define GNIT    (GK / BK)       // 32
#define STAGES  3
#define BM_CTA  256
#define BN_CTA  128
#define LDT     40
#define A_FLTS  (BM_CTA * LDT)                 // 10240 floats per A stage
#define B_FLTS  (BN_CTA * LDT)                 // 5120 floats per B stage
#define STG_FLTS (A_FLTS + B_FLTS)             // 15360
#define GEMM_SMEM_BYTES (STAGES * STG_FLTS * 4)  // 184320

__device__ __forceinline__ void mma_tf32(float c[4], const uint32_t a[4],
                                         const uint32_t b[2])
{
    asm volatile(
        "mma.sync.aligned.m16n8k8.row.col.f32.tf32.tf32.f32 "
        "{%0,%1,%2,%3}, {%4,%5,%6,%7}, {%8,%9}, {%0,%1,%2,%3};"
        : "+f"(c[0]), "+f"(c[1]), "+f"(c[2]), "+f"(c[3])
        : "r"(a[0]), "r"(a[1]), "r"(a[2]), "r"(a[3]), "r"(b[0]), "r"(b[1]));
}

__global__ void __launch_bounds__(256, 1)
gemm_mma(const float* __restrict__ A, const float* __restrict__ B,
         float* __restrict__ C, int N)
{
    extern __shared__ float smem[];   // [STAGES][A_FLTS + B_FLTS]

    const int tid  = threadIdx.x;
    const int wid  = tid >> 5;
    const int lane = tid & 31;
    const int g    = lane >> 2;
    const int t4   = lane & 3;
    const int warpM = wid & 3;        // 0..3 -> 64 rows each (256 total)
    const int warpN = wid >> 2;       // 0..1 -> 64 cols each (128 total)

    const float* Ab = A + (size_t)blockIdx.y * BM_CTA * GK;
    const float* Bb = B + (size_t)blockIdx.x * BN_CTA * GK;

    const uint32_t smem_u = (uint32_t)__cvta_generic_to_shared(smem);

    // Loader mapping (per stage): A = 2048 float4 (8/thread), B = 1024 float4 (4/thread)
    int arow[8], acf[8];
    #pragma unroll
    for (int j = 0; j < 8; j++) {
        const int lin = tid + j * 256;
        arow[j] = lin >> 3;             // 0..255
        acf[j]  = (lin & 7) * 4;        // float offset in 32-float row
    }
    int brow[4], bcf[4];
    #pragma unroll
    for (int j = 0; j < 4; j++) {
        const int lin = tid + j * 256;
        brow[j] = lin >> 3;             // 0..127
        bcf[j]  = (lin & 7) * 4;
    }

    float acc[4][8][4];
    #pragma unroll
    for (int i = 0; i < 4; i++)
        #pragma unroll
        for (int j = 0; j < 8; j++)
            #pragma unroll
            for (int r = 0; r < 4; r++) acc[i][j][r] = 0.f;

    // Prologue: fill stages 0,1 (groups #0, #1)
    #pragma unroll
    for (int p = 0; p < 2; p++) {
        const int k0 = p * BK;
        const uint32_t soA = (uint32_t)(p * STG_FLTS) * 4u;
        const uint32_t soB = soA + (uint32_t)A_FLTS * 4u;
        #pragma unroll
        for (int j = 0; j < 8; j++)
            cp_async16(smem_u + soA + (uint32_t)((arow[j] * LDT + acf[j]) * 4),
                       Ab + (size_t)arow[j] * GK + k0 + acf[j]);
        #pragma unroll
        for (int j = 0; j < 4; j++)
            cp_async16(smem_u + soB + (uint32_t)((brow[j] * LDT + bcf[j]) * 4),
                       Bb + (size_t)brow[j] * GK + k0 + bcf[j]);
        asm volatile("cp.async.commit_group;" ::: "memory");
    }

    int cur = 0;                       // stage to compute this iter (group #it)
    int nf  = 2;                       // stage to fill this iter (tile it+2)
    #pragma unroll 1
    for (int it = 0; it < GNIT; it++) {
        // Wait for stage cur's group (committed 2 groups back; <=1 newer pending),
        // THEN barrier so every thread sees every thread's copies. This ordering
        // (wait -> barrier) is what makes cp.async data cross-thread visible.
        asm volatile("cp.async.wait_group 1;" ::: "memory");
        __syncthreads();
        // The barrier also proves all warps finished computing stage nf at iter
        // it-1, so filling it now is safe.

        // Fill stage nf with tile it+2 — overlaps with the MMAs below.
        if (it + 2 < GNIT) {
            const int k0 = (it + 2) * BK;
            const uint32_t soA = (uint32_t)(nf * STG_FLTS) * 4u;
            const uint32_t soB = soA + (uint32_t)A_FLTS * 4u;
            #pragma unroll
            for (int j = 0; j < 8; j++)
                cp_async16(smem_u + soA + (uint32_t)((arow[j] * LDT + acf[j]) * 4),
                           Ab + (size_t)arow[j] * GK + k0 + acf[j]);
            #pragma unroll
            for (int j = 0; j < 4; j++)
                cp_async16(smem_u + soB + (uint32_t)((brow[j] * LDT + bcf[j]) * 4),
                           Bb + (size_t)brow[j] * GK + k0 + bcf[j]);
        }
        asm volatile("cp.async.commit_group;" ::: "memory");   // keep group count static

        const float* As = smem + cur * STG_FLTS;
        const float* Bs = As + A_FLTS;
        #pragma unroll
        for (int ko = 0; ko < BK; ko += 8) {
            // Permuted layout: orig cols (t4, t4+4) sit adjacent at ko + 2*t4
            uint32_t af[4][4];
            #pragma unroll
            for (int mf = 0; mf < 4; mf++) {
                const int rb = warpM * 64 + mf * 16 + g;
                const float2 a01 = *reinterpret_cast<const float2*>(&As[rb * LDT + ko + 2 * t4]);
                const float2 a23 = *reinterpret_cast<const float2*>(&As[(rb + 8) * LDT + ko + 2 * t4]);
                af[mf][0] = __float_as_uint(a01.x);
                af[mf][1] = __float_as_uint(a23.x);
                af[mf][2] = __float_as_uint(a01.y);
                af[mf][3] = __float_as_uint(a23.y);
            }
            uint32_t bf[8][2];
            #pragma unroll
            for (int nfr = 0; nfr < 8; nfr++) {
                const int nb = warpN * 64 + nfr * 8 + g;
                const float2 b01 = *reinterpret_cast<const float2*>(&Bs[nb * LDT + ko + 2 * t4]);
                bf[nfr][0] = __float_as_uint(b01.x);
                bf[nfr][1] = __float_as_uint(b01.y);
            }
            #pragma unroll
            for (int mf = 0; mf < 4; mf++)
                #pragma unroll
                for (int nfr = 0; nfr < 8; nfr++)
                    mma_tf32(acc[mf][nfr], af[mf], bf[nfr]);
        }

        cur = (cur == STAGES - 1) ? 0 : cur + 1;
        nf  = (nf  == STAGES - 1) ? 0 : nf  + 1;
    }

    // Epilogue: direct float2 stores
    const int m0 = blockIdx.y * BM_CTA + warpM * 64;
    const int n0 = blockIdx.x * BN_CTA + warpN * 64;
    #pragma unroll
    for (int mf = 0; mf < 4; mf++) {
        const int r0 = m0 + mf * 16 + g;
        #pragma unroll
        for (int nfr = 0; nfr < 8; nfr++) {
            const int c0 = n0 + nfr * 8 + t4 * 2;
            *reinterpret_cast<float2*>(C + (size_t)r0 * N + c0) =
                make_float2(acc[mf][nfr][0], acc[mf][nfr][1]);
            *reinterpret_cast<float2*>(C + (size_t)(r0 + 8) * N + c0) =
                make_float2(acc[mf][nfr][2], acc[mf][nfr][3]);
        }
    }
}

// ---------------------------------------------------------------------------
// Attention: one block per (n, h); 16-frame causal attention with RoPE.
// Output written tf32-rounded + K-permuted (it feeds the out-proj GEMM).
// ---------------------------------------------------------------------------
__global__ void __launch_bounds__(64) attn_kernel()
{
    const int nh = blockIdx.x;
    const int n  = nh >> 4;
    const int h  = nh & 15;
    const int b  = n >> 10;
    const int s  = n & 1023;
    const int d  = threadIdx.x;

    __shared__ float qs[FRAMES][HDIM + 1];
    __shared__ float ks[FRAMES][HDIM + 1];
    __shared__ float vs[FRAMES][HDIM];
    __shared__ float ssm[FRAMES][FRAMES];

    const int col = h * HDIM + d;
    #pragma unroll
    for (int t = 0; t < FRAMES; t++) {
        const size_t row = (size_t)((b * FRAMES + t) * SPATIAL + s) * QKV_N;
        qs[t][d] = g_qkv[row + col];
        ks[t][d] = g_qkv[row + HIDDEN + col];
        vs[t][d] = g_qkv[row + 2 * HIDDEN + col];
    }
    __syncthreads();

    const int i = d & 31;
    const float inv_freq = expf(-(float)(2 * i) * (9.210340371976184f / 64.0f));
    float qr[FRAMES], kr[FRAMES];
    #pragma unroll
    for (int t = 0; t < FRAMES; t++) {
        const float fr = (float)t * inv_freq;
        const float c  = cosf(fr);
        const float sn = sinf(fr);
        const float rotq = (d < 32) ? -qs[t][d + 32] : qs[t][d - 32];
        const float rotk = (d < 32) ? -ks[t][d + 32] : ks[t][d - 32];
        qr[t] = qs[t][d] * c + rotq * sn;
        kr[t] = ks[t][d] * c + rotk * sn;
    }
    __syncthreads();
    #pragma unroll
    for (int t = 0; t < FRAMES; t++) { qs[t][d] = qr[t]; ks[t][d] = kr[t]; }
    __syncthreads();

    #pragma unroll
    for (int idx = d; idx < FRAMES * FRAMES; idx += 64) {
        const int tq = idx >> 4;
        const int tk = idx & 15;
        float a;
        if (tk <= tq) {
            a = 0.f;
            #pragma unroll
            for (int e = 0; e < HDIM; e++) a += qs[tq][e] * ks[tk][e];
            a *= 0.125f;
        } else {
            a = -INFINITY;
        }
        ssm[tq][tk] = a;
    }
    __syncthreads();

    if (d < FRAMES) {
        float m = ssm[d][0];
        for (int k = 1; k <= d; k++) m = fmaxf(m, ssm[d][k]);
        float sum = 0.f;
        for (int k = 0; k <= d; k++) {
            const float e = expf(ssm[d][k] - m);
            ssm[d][k] = e;
            sum += e;
        }
        const float r = 1.0f / sum;
        for (int k = 0; k <= d; k++) ssm[d][k] *= r;
        for (int k = d + 1; k < FRAMES; k++) ssm[d][k] = 0.f;
    }
    __syncthreads();

    const int dp = h * HDIM + kperm(d);   // permuted destination column
    #pragma unroll
    for (int t = 0; t < FRAMES; t++) {
        float a = 0.f;
        #pragma unroll
        for (int k = 0; k < FRAMES; k++) a += ssm[t][k] * vs[k][d];
        g_attn[(size_t)((b * FRAMES + t) * SPATIAL + s) * HIDDEN + dp] = to_tf32(a);
    }
}

// ---------------------------------------------------------------------------
// Launch
// ---------------------------------------------------------------------------
extern "C" void kernel_launch(void* const* d_in, const int* in_sizes, int n_in,
                              void* d_out, int out_size)
{
    const float* x      = (const float*)d_in[0];
    const float* w_qkv  = (const float*)d_in[1];
    const float* w_out  = (const float*)d_in[2];
    const float* gamma  = (const float*)d_in[3];
    const float* beta   = (const float*)d_in[4];

    float* xn_p;    cudaGetSymbolAddress((void**)&xn_p,    g_xn);
    float* qkv_p;   cudaGetSymbolAddress((void**)&qkv_p,   g_qkv);
    float* attn_p;  cudaGetSymbolAddress((void**)&attn_p,  g_attn);
    float* wqkv_p;  cudaGetSymbolAddress((void**)&wqkv_p,  g_wqkv_r);
    float* wout_p;  cudaGetSymbolAddress((void**)&wout_p,  g_wout_r);

    cudaFuncSetAttribute(gemm_mma, cudaFuncAttributeMaxDynamicSharedMemorySize,
                         GEMM_SMEM_BYTES);

    // 0) Round+permute weights (tiny)
    round_perm_w<<<(QKV_N * HIDDEN) / 256, 256>>>(w_qkv, wqkv_p);
    round_perm_w<<<(HIDDEN * HIDDEN) / 256, 256>>>(w_out, wout_p);

    // 1) LayerNorm (outputs rounded+permuted)
    ln_kernel<<<NTOK, 256>>>(x, gamma, beta);

    // 2) QKV projection [tf32 mma.sync + 3-stage cp.async pipeline]
    gemm_mma<<<dim3(QKV_N / BN_CTA, NTOK / BM_CTA), 256, GEMM_SMEM_BYTES>>>(
        xn_p, wqkv_p, qkv_p, QKV_N);

    // 3) Attention (RoPE + causal softmax + PV); outputs rounded+permuted
    attn_kernel<<<NTOK, 64>>>();

    // 4) Output projection -> d_out
    gemm_mma<<<dim3(HIDDEN / BN_CTA, NTOK / BM_CTA), 256, GEMM_SMEM_BYTES>>>(
        attn_p, wout_p, (float*)d_out, HIDDEN);
}

// round 12
// speedup vs baseline: 1.6811x; 1.6811x over previous
#include <cuda_runtime.h>
#include <cuda_fp16.h>
#include <math.h>
#include <stdint.h>

// Problem constants (hardcoded from reference setup_inputs)
#define BATCH   2
#define FRAMES  16
#define SPATIAL 1024            // height*width = 32*32
#define HIDDEN  1024
#define NHEADS  16
#define HDIM    64
#define NTOK    (BATCH*FRAMES*SPATIAL)   // 32768
#define QKV_N   (3*HIDDEN)               // 3072
#define LN_EPS  1e-5f

// Scratch buffers (device globals; no runtime allocation allowed)
__device__ __half g_xn_h[(size_t)NTOK * HIDDEN];      // 64 MB (fp16, pair-permuted)
__device__ float  g_qkv[(size_t)NTOK * QKV_N];        // 402 MB (fp32, natural)
__device__ __half g_attn_h[(size_t)NTOK * HIDDEN];    // 64 MB (fp16, pair-permuted)
__device__ __half g_wqkv_h[(size_t)QKV_N * HIDDEN];   // 6 MB  (fp16, pair-permuted)
__device__ __half g_wout_h[(size_t)HIDDEN * HIDDEN];  // 2 MB  (fp16, pair-permuted)

// Pair-level K-permutation: within each 16-element k-group (8 fp16 pairs),
// pair p -> slot (p<4 ? 2p : 2(p-4)+1). Fragment pairs (t4, t4+4) land adjacent.
__device__ __forceinline__ int pslot(int p) {   // p in 0..7
    return (p < 4) ? (2 * p) : (2 * (p - 4) + 1);
}

__device__ __forceinline__ void cp_async16(uint32_t saddr, const void* gaddr) {
    asm volatile("cp.async.cg.shared.global [%0], [%1], 16;" :: "r"(saddr), "l"(gaddr));
}

// ---------------------------------------------------------------------------
// Weight round+permute: fp32 row-major [rows,1024] -> fp16 pair-permuted.
// One block per row, 256 threads, 4 cols each (2 pairs -> 2 half2 stores).
// ---------------------------------------------------------------------------
__global__ void __launch_bounds__(256) round_perm_w_h(const float* __restrict__ w,
                                                      __half2* __restrict__ out)
{
    const int row = blockIdx.x;
    const int tid = threadIdx.x;
    const float4 v = reinterpret_cast<const float4*>(w + (size_t)row * HIDDEN)[tid];
    const int g16  = tid >> 2;                 // 16-elem group index (8 half2 words)
    const int pl   = 2 * (tid & 3);            // first pair index within group
    __half2* obase = out + (size_t)row * (HIDDEN / 2) + g16 * 8;
    obase[pslot(pl)]     = __floats2half2_rn(v.x, v.y);
    obase[pslot(pl + 1)] = __floats2half2_rn(v.z, v.w);
}

// ---------------------------------------------------------------------------
// LayerNorm: one block per token; output fp16 pair-permuted
// ---------------------------------------------------------------------------
__global__ void __launch_bounds__(256) ln_kernel(const float* __restrict__ x,
                                                 const float* __restrict__ gamma,
                                                 const float* __restrict__ beta)
{
    const int tok = blockIdx.x;
    const int tid = threadIdx.x;
    const float4* xr = reinterpret_cast<const float4*>(x + (size_t)tok * HIDDEN);
    float4 v = xr[tid];

    float s  = v.x + v.y + v.z + v.w;
    float ss = v.x*v.x + v.y*v.y + v.z*v.z + v.w*v.w;

    #pragma unroll
    for (int o = 16; o > 0; o >>= 1) {
        s  += __shfl_xor_sync(0xffffffffu, s,  o);
        ss += __shfl_xor_sync(0xffffffffu, ss, o);
    }
    __shared__ float red_s[8], red_ss[8];
    const int warp = tid >> 5, lane = tid & 31;
    if (lane == 0) { red_s[warp] = s; red_ss[warp] = ss; }
    __syncthreads();
    float fs = 0.f, fss = 0.f;
    #pragma unroll
    for (int i = 0; i < 8; i++) { fs += red_s[i]; fss += red_ss[i]; }

    const float mean = fs * (1.0f / HIDDEN);
    const float var  = fss * (1.0f / HIDDEN) - mean * mean;
    const float inv  = rsqrtf(var + LN_EPS);

    const float4 gm = reinterpret_cast<const float4*>(gamma)[tid];
    const float4 bt = reinterpret_cast<const float4*>(beta)[tid];
    const float o0 = (v.x - mean) * inv * gm.x + bt.x;
    const float o1 = (v.y - mean) * inv * gm.y + bt.y;
    const float o2 = (v.z - mean) * inv * gm.z + bt.z;
    const float o3 = (v.w - mean) * inv * gm.w + bt.w;

    const int g16 = tid >> 2;
    const int pl  = 2 * (tid & 3);
    __half2* obase = reinterpret_cast<__half2*>(g_xn_h) + (size_t)tok * (HIDDEN / 2) + g16 * 8;
    obase[pslot(pl)]     = __floats2half2_rn(o0, o1);
    obase[pslot(pl + 1)] = __floats2half2_rn(o2, o3);
}

// ---------------------------------------------------------------------------
// FP16 mma.sync GEMM (NT), K=1024: C[m][n] = sum_k A[m][k]*B[n][k]
// A, B fp16 pair-permuted. CTA tile 128x128, BK=64 fp16, 128 threads =
// 4 warps (2Mx2N), warp tile 64x64 of m16n8k16. 2-stage cp.async pipeline.
// smem row stride LDTW=40 words (32 data + 8 pad) -> conflict-free LDS.64.
// ---------------------------------------------------------------------------
#define HK      1024
#define HBK     64
#define HNIT    (HK / HBK)      // 16
#define LDTW    40              // 4-byte words per smem row
#define AW      (128 * LDTW)    // words per matrix per stage (5120)
#define STGW    (2 * AW)        // words per stage (A+B)
#define GEMM_SMEM_BYTES (2 * STGW * 4)   // 81920

__device__ __forceinline__ void mma_f16(float c[4],
                                        uint32_t a0, uint32_t a1, uint32_t a2, uint32_t a3,
                                        uint32_t b0, uint32_t b1)
{
    asm volatile(
        "mma.sync.aligned.m16n8k16.row.col.f32.f16.f16.f32 "
        "{%0,%1,%2,%3}, {%4,%5,%6,%7}, {%8,%9}, {%0,%1,%2,%3};"
        : "+f"(c[0]), "+f"(c[1]), "+f"(c[2]), "+f"(c[3])
        : "r"(a0), "r"(a1), "r"(a2), "r"(a3), "r"(b0), "r"(b1));
}

__global__ void __launch_bounds__(128, 2)
gemm_h(const __half* __restrict__ A, const __half* __restrict__ B,
       float* __restrict__ C, int N)
{
    extern __shared__ uint32_t smem[];   // [2][STGW] words

    const int tid  = threadIdx.x;
    const int wid  = tid >> 5;
    const int lane = tid & 31;
    const int g    = lane >> 2;
    const int t4   = lane & 3;
    const int warpM = wid & 1;        // 0..1 -> 64 rows
    const int warpN = wid >> 1;       // 0..1 -> 64 cols

    const __half* Ab = A + (size_t)blockIdx.y * 128 * HK;
    const __half* Bb = B + (size_t)blockIdx.x * 128 * HK;

    const uint32_t smem_u = (uint32_t)__cvta_generic_to_shared(smem);

    // Loader mapping: per matrix per stage 128 rows x 8 chunks(16B) = 1024;
    // 128 threads -> 8 chunks/thread/matrix.
    int lrow[8], lch[8];
    #pragma unroll
    for (int j = 0; j < 8; j++) {
        const int lin = tid + j * 128;
        lrow[j] = lin >> 3;
        lch[j]  = lin & 7;
    }

    float acc[4][8][4];
    #pragma unroll
    for (int i = 0; i < 4; i++)
        #pragma unroll
        for (int j = 0; j < 8; j++)
            #pragma unroll
            for (int r = 0; r < 4; r++) acc[i][j][r] = 0.f;

    // Prologue: fill stage 0 with tile 0
    #pragma unroll
    for (int j = 0; j < 8; j++) {
        cp_async16(smem_u + (uint32_t)((lrow[j] * LDTW + lch[j] * 4) * 4),
                   Ab + (size_t)lrow[j] * HK + lch[j] * 8);
        cp_async16(smem_u + (uint32_t)((AW + lrow[j] * LDTW + lch[j] * 4) * 4),
                   Bb + (size_t)lrow[j] * HK + lch[j] * 8);
    }
    asm volatile("cp.async.commit_group;" ::: "memory");

    #pragma unroll 1
    for (int it = 0; it < HNIT; it++) {
        const int cur = it & 1;
        const int nxt = cur ^ 1;

        // All warps finished computing stage nxt's previous contents
        __syncthreads();

        // Fill stage nxt with tile it+1 (overlaps MMAs below)
        if (it + 1 < HNIT) {
            const int k0 = (it + 1) * HBK;
            const uint32_t so = (uint32_t)(nxt * STGW) * 4u;
            #pragma unroll
            for (int j = 0; j < 8; j++) {
                cp_async16(smem_u + so + (uint32_t)((lrow[j] * LDTW + lch[j] * 4) * 4),
                           Ab + (size_t)lrow[j] * HK + k0 + lch[j] * 8);
                cp_async16(smem_u + so + (uint32_t)((AW + lrow[j] * LDTW + lch[j] * 4) * 4),
                           Bb + (size_t)lrow[j] * HK + k0 + lch[j] * 8);
            }
        }
        asm volatile("cp.async.commit_group;" ::: "memory");

        // Complete stage cur's group; then barrier for cross-thread visibility
        asm volatile("cp.async.wait_group 1;" ::: "memory");
        __syncthreads();

        const uint32_t* As = smem + cur * STGW;
        const uint32_t* Bs = As + AW;
        #pragma unroll
        for (int kg = 0; kg < HBK / 16; kg++) {     // 4 k16-steps
            const int kb = kg * 8;                  // word base of k-group
            uint32_t af[4][4];
            #pragma unroll
            for (int mf = 0; mf < 4; mf++) {
                const int rb = warpM * 64 + mf * 16 + g;
                const uint2 lo = *reinterpret_cast<const uint2*>(&As[rb * LDTW + kb + 2 * t4]);
                const uint2 hi = *reinterpret_cast<const uint2*>(&As[(rb + 8) * LDTW + kb + 2 * t4]);
                af[mf][0] = lo.x;   // rows g,   k 2t4..2t4+1
                af[mf][1] = hi.x;   // rows g+8
                af[mf][2] = lo.y;   // rows g,   k 2t4+8..2t4+9
                af[mf][3] = hi.y;   // rows g+8
            }
            uint32_t bf[8][2];
            #pragma unroll
            for (int nfr = 0; nfr < 8; nfr++) {
                const int nb = warpN * 64 + nfr * 8 + g;
                const uint2 bb = *reinterpret_cast<const uint2*>(&Bs[nb * LDTW + kb + 2 * t4]);
                bf[nfr][0] = bb.x;
                bf[nfr][1] = bb.y;
            }
            #pragma unroll
            for (int mf = 0; mf < 4; mf++)
                #pragma unroll
                for (int nfr = 0; nfr < 8; nfr++)
                    mma_f16(acc[mf][nfr], af[mf][0], af[mf][1], af[mf][2], af[mf][3],
                            bf[nfr][0], bf[nfr][1]);
        }
    }

    // Epilogue: direct float2 stores
    const int m0 = blockIdx.y * 128 + warpM * 64;
    const int n0 = blockIdx.x * 128 + warpN * 64;
    #pragma unroll
    for (int mf = 0; mf < 4; mf++) {
        const int r0 = m0 + mf * 16 + g;
        #pragma unroll
        for (int nfr = 0; nfr < 8; nfr++) {
            const int c0 = n0 + nfr * 8 + t4 * 2;
            *reinterpret_cast<float2*>(C + (size_t)r0 * N + c0) =
                make_float2(acc[mf][nfr][0], acc[mf][nfr][1]);
            *reinterpret_cast<float2*>(C + (size_t)(r0 + 8) * N + c0) =
                make_float2(acc[mf][nfr][2], acc[mf][nfr][3]);
        }
    }
}

// ---------------------------------------------------------------------------
// Attention: one block per (n, h); 16-frame causal attention with RoPE.
// Reads fp32 qkv; writes fp16 pair-permuted attn output.
// ---------------------------------------------------------------------------
__global__ void __launch_bounds__(64) attn_kernel()
{
    const int nh = blockIdx.x;
    const int n  = nh >> 4;
    const int h  = nh & 15;
    const int b  = n >> 10;
    const int s  = n & 1023;
    const int d  = threadIdx.x;

    __shared__ float qs[FRAMES][HDIM + 1];
    __shared__ float ks[FRAMES][HDIM + 1];
    __shared__ float vs[FRAMES][HDIM];
    __shared__ float ssm[FRAMES][FRAMES];

    const int col = h * HDIM + d;
    #pragma unroll
    for (int t = 0; t < FRAMES; t++) {
        const size_t row = (size_t)((b * FRAMES + t) * SPATIAL + s) * QKV_N;
        qs[t][d] = g_qkv[row + col];
        ks[t][d] = g_qkv[row + HIDDEN + col];
        vs[t][d] = g_qkv[row + 2 * HIDDEN + col];
    }
    __syncthreads();

    const int i = d & 31;
    const float inv_freq = expf(-(float)(2 * i) * (9.210340371976184f / 64.0f));
    float qr[FRAMES], kr[FRAMES];
    #pragma unroll
    for (int t = 0; t < FRAMES; t++) {
        const float fr = (float)t * inv_freq;
        const float c  = cosf(fr);
        const float sn = sinf(fr);
        const float rotq = (d < 32) ? -qs[t][d + 32] : qs[t][d - 32];
        const float rotk = (d < 32) ? -ks[t][d + 32] : ks[t][d - 32];
        qr[t] = qs[t][d] * c + rotq * sn;
        kr[t] = ks[t][d] * c + rotk * sn;
    }
    __syncthreads();
    #pragma unroll
    for (int t = 0; t < FRAMES; t++) { qs[t][d] = qr[t]; ks[t][d] = kr[t]; }
    __syncthreads();

    #pragma unroll
    for (int idx = d; idx < FRAMES * FRAMES; idx += 64) {
        const int tq = idx >> 4;
        const int tk = idx & 15;
        float a;
        if (tk <= tq) {
            a = 0.f;
            #pragma unroll
            for (int e = 0; e < HDIM; e++) a += qs[tq][e] * ks[tk][e];
            a *= 0.125f;
        } else {
            a = -INFINITY;
        }
        ssm[tq][tk] = a;
    }
    __syncthreads();

    if (d < FRAMES) {
        float m = ssm[d][0];
        for (int k = 1; k <= d; k++) m = fmaxf(m, ssm[d][k]);
        float sum = 0.f;
        for (int k = 0; k <= d; k++) {
            const float e = expf(ssm[d][k] - m);
            ssm[d][k] = e;
            sum += e;
        }
        const float r = 1.0f / sum;
        for (int k = 0; k <= d; k++) ssm[d][k] *= r;
        for (int k = d + 1; k < FRAMES; k++) ssm[d][k] = 0.f;
    }
    __syncthreads();

    // Permuted fp16 destination: element index within head = pair-permuted d
    const int g16  = d >> 4;
    const int pl   = (d >> 1) & 7;
    const int dp   = h * HDIM + g16 * 16 + pslot(pl) * 2 + (d & 1);
    #pragma unroll
    for (int t = 0; t < FRAMES; t++) {
        float a = 0.f;
        #pragma unroll
        for (int k = 0; k < FRAMES; k++) a += ssm[t][k] * vs[k][d];
        g_attn_h[(size_t)((b * FRAMES + t) * SPATIAL + s) * HIDDEN + dp] = __float2half_rn(a);
    }
}

// ---------------------------------------------------------------------------
// Launch
// ---------------------------------------------------------------------------
extern "C" void kernel_launch(void* const* d_in, const int* in_sizes, int n_in,
                              void* d_out, int out_size)
{
    const float* x      = (const float*)d_in[0];
    const float* w_qkv  = (const float*)d_in[1];
    const float* w_out  = (const float*)d_in[2];
    const float* gamma  = (const float*)d_in[3];
    const float* beta   = (const float*)d_in[4];

    __half* xn_p;   cudaGetSymbolAddress((void**)&xn_p,   g_xn_h);
    float*  qkv_p;  cudaGetSymbolAddress((void**)&qkv_p,  g_qkv);
    __half* attn_p; cudaGetSymbolAddress((void**)&attn_p, g_attn_h);
    __half* wqkv_p; cudaGetSymbolAddress((void**)&wqkv_p, g_wqkv_h);
    __half* wout_p; cudaGetSymbolAddress((void**)&wout_p, g_wout_h);

    cudaFuncSetAttribute(gemm_h, cudaFuncAttributeMaxDynamicSharedMemorySize,
                         GEMM_SMEM_BYTES);

    // 0) Round+permute weights to fp16 (tiny)
    round_perm_w_h<<<QKV_N, 256>>>(w_qkv, (__half2*)wqkv_p);
    round_perm_w_h<<<HIDDEN, 256>>>(w_out, (__half2*)wout_p);

    // 1) LayerNorm -> fp16 permuted
    ln_kernel<<<NTOK, 256>>>(x, gamma, beta);

    // 2) QKV projection [fp16 m16n8k16 mma + cp.async pipeline] -> fp32 qkv
    gemm_h<<<dim3(QKV_N / 128, NTOK / 128), 128, GEMM_SMEM_BYTES>>>(
        xn_p, wqkv_p, qkv_p, QKV_N);

    // 3) Attention (RoPE + causal softmax + PV) -> fp16 permuted
    attn_kernel<<<NTOK, 64>>>();

    // 4) Output projection -> d_out (fp32)
    gemm_h<<<dim3(HIDDEN / 128, NTOK / 128), 128, GEMM_SMEM_BYTES>>>(
        attn_p, wout_p, (float*)d_out, HIDDEN);
}

// round 13
// speedup vs baseline: 1.6881x; 1.0042x over previous
#include <cuda_runtime.h>
#include <cuda_fp16.h>
#include <math.h>
#include <stdint.h>

// Problem constants (hardcoded from reference setup_inputs)
#define BATCH   2
#define FRAMES  16
#define SPATIAL 1024            // height*width = 32*32
#define HIDDEN  1024
#define NHEADS  16
#define HDIM    64
#define NTOK    (BATCH*FRAMES*SPATIAL)   // 32768
#define QKV_N   (3*HIDDEN)               // 3072
#define LN_EPS  1e-5f

// Scratch buffers (device globals; no runtime allocation allowed)
__device__ __half g_xn_h[(size_t)NTOK * HIDDEN];      // 64 MB  (fp16, pair-permuted)
__device__ __half g_qkv_h[(size_t)NTOK * QKV_N];      // 201 MB (fp16, natural layout)
__device__ __half g_attn_h[(size_t)NTOK * HIDDEN];    // 64 MB  (fp16, pair-permuted)
__device__ __half g_wqkv_h[(size_t)QKV_N * HIDDEN];   // 6 MB   (fp16, pair-permuted)
__device__ __half g_wout_h[(size_t)HIDDEN * HIDDEN];  // 2 MB   (fp16, pair-permuted)

// Pair-level K-permutation: within each 16-element k-group (8 fp16 pairs),
// pair p -> slot (p<4 ? 2p : 2(p-4)+1). Fragment pairs (t4, t4+4) land adjacent.
__device__ __forceinline__ int pslot(int p) {   // p in 0..7
    return (p < 4) ? (2 * p) : (2 * (p - 4) + 1);
}

__device__ __forceinline__ void cp_async16(uint32_t saddr, const void* gaddr) {
    asm volatile("cp.async.cg.shared.global [%0], [%1], 16;" :: "r"(saddr), "l"(gaddr));
}

// ---------------------------------------------------------------------------
// Weight round+permute: fp32 row-major [rows,1024] -> fp16 pair-permuted.
// ---------------------------------------------------------------------------
__global__ void __launch_bounds__(256) round_perm_w_h(const float* __restrict__ w,
                                                      __half2* __restrict__ out)
{
    const int row = blockIdx.x;
    const int tid = threadIdx.x;
    const float4 v = reinterpret_cast<const float4*>(w + (size_t)row * HIDDEN)[tid];
    const int g16  = tid >> 2;                 // 16-elem group index (8 half2 words)
    const int pl   = 2 * (tid & 3);            // first pair index within group
    __half2* obase = out + (size_t)row * (HIDDEN / 2) + g16 * 8;
    obase[pslot(pl)]     = __floats2half2_rn(v.x, v.y);
    obase[pslot(pl + 1)] = __floats2half2_rn(v.z, v.w);
}

// ---------------------------------------------------------------------------
// LayerNorm: one block per token; output fp16 pair-permuted
// ---------------------------------------------------------------------------
__global__ void __launch_bounds__(256) ln_kernel(const float* __restrict__ x,
                                                 const float* __restrict__ gamma,
                                                 const float* __restrict__ beta)
{
    const int tok = blockIdx.x;
    const int tid = threadIdx.x;
    const float4* xr = reinterpret_cast<const float4*>(x + (size_t)tok * HIDDEN);
    float4 v = xr[tid];

    float s  = v.x + v.y + v.z + v.w;
    float ss = v.x*v.x + v.y*v.y + v.z*v.z + v.w*v.w;

    #pragma unroll
    for (int o = 16; o > 0; o >>= 1) {
        s  += __shfl_xor_sync(0xffffffffu, s,  o);
        ss += __shfl_xor_sync(0xffffffffu, ss, o);
    }
    __shared__ float red_s[8], red_ss[8];
    const int warp = tid >> 5, lane = tid & 31;
    if (lane == 0) { red_s[warp] = s; red_ss[warp] = ss; }
    __syncthreads();
    float fs = 0.f, fss = 0.f;
    #pragma unroll
    for (int i = 0; i < 8; i++) { fs += red_s[i]; fss += red_ss[i]; }

    const float mean = fs * (1.0f / HIDDEN);
    const float var  = fss * (1.0f / HIDDEN) - mean * mean;
    const float inv  = rsqrtf(var + LN_EPS);

    const float4 gm = reinterpret_cast<const float4*>(gamma)[tid];
    const float4 bt = reinterpret_cast<const float4*>(beta)[tid];
    const float o0 = (v.x - mean) * inv * gm.x + bt.x;
    const float o1 = (v.y - mean) * inv * gm.y + bt.y;
    const float o2 = (v.z - mean) * inv * gm.z + bt.z;
    const float o3 = (v.w - mean) * inv * gm.w + bt.w;

    const int g16 = tid >> 2;
    const int pl  = 2 * (tid & 3);
    __half2* obase = reinterpret_cast<__half2*>(g_xn_h) + (size_t)tok * (HIDDEN / 2) + g16 * 8;
    obase[pslot(pl)]     = __floats2half2_rn(o0, o1);
    obase[pslot(pl + 1)] = __floats2half2_rn(o2, o3);
}

// ---------------------------------------------------------------------------
// FP16 mma.sync GEMM (NT), K=1024: C[m][n] = sum_k A[m][k]*B[n][k]
// A, B fp16 pair-permuted. CTA tile 128x128, BK=64 fp16, 128 threads =
// 4 warps (2Mx2N), warp tile 64x64 of m16n8k16. 2-stage cp.async pipeline.
// F16OUT: C stored as __half2 (QKV path); else fp32 (final output).
// ---------------------------------------------------------------------------
#define HK      1024
#define HBK     64
#define HNIT    (HK / HBK)      // 16
#define LDTW    40              // 4-byte words per smem row
#define AW      (128 * LDTW)    // words per matrix per stage (5120)
#define STGW    (2 * AW)        // words per stage (A+B)
#define GEMM_SMEM_BYTES (2 * STGW * 4)   // 81920

__device__ __forceinline__ void mma_f16(float c[4],
                                        uint32_t a0, uint32_t a1, uint32_t a2, uint32_t a3,
                                        uint32_t b0, uint32_t b1)
{
    asm volatile(
        "mma.sync.aligned.m16n8k16.row.col.f32.f16.f16.f32 "
        "{%0,%1,%2,%3}, {%4,%5,%6,%7}, {%8,%9}, {%0,%1,%2,%3};"
        : "+f"(c[0]), "+f"(c[1]), "+f"(c[2]), "+f"(c[3])
        : "r"(a0), "r"(a1), "r"(a2), "r"(a3), "r"(b0), "r"(b1));
}

template<bool F16OUT>
__global__ void __launch_bounds__(128, 2)
gemm_h(const __half* __restrict__ A, const __half* __restrict__ B,
       void* __restrict__ Cv, int N)
{
    extern __shared__ uint32_t smem[];   // [2][STGW] words

    const int tid  = threadIdx.x;
    const int wid  = tid >> 5;
    const int lane = tid & 31;
    const int g    = lane >> 2;
    const int t4   = lane & 3;
    const int warpM = wid & 1;        // 0..1 -> 64 rows
    const int warpN = wid >> 1;       // 0..1 -> 64 cols

    const __half* Ab = A + (size_t)blockIdx.y * 128 * HK;
    const __half* Bb = B + (size_t)blockIdx.x * 128 * HK;

    const uint32_t smem_u = (uint32_t)__cvta_generic_to_shared(smem);

    // Loader mapping: per matrix per stage 128 rows x 8 chunks(16B) = 1024;
    // 128 threads -> 8 chunks/thread/matrix.
    int lrow[8], lch[8];
    #pragma unroll
    for (int j = 0; j < 8; j++) {
        const int lin = tid + j * 128;
        lrow[j] = lin >> 3;
        lch[j]  = lin & 7;
    }

    float acc[4][8][4];
    #pragma unroll
    for (int i = 0; i < 4; i++)
        #pragma unroll
        for (int j = 0; j < 8; j++)
            #pragma unroll
            for (int r = 0; r < 4; r++) acc[i][j][r] = 0.f;

    // Prologue: fill stage 0 with tile 0
    #pragma unroll
    for (int j = 0; j < 8; j++) {
        cp_async16(smem_u + (uint32_t)((lrow[j] * LDTW + lch[j] * 4) * 4),
                   Ab + (size_t)lrow[j] * HK + lch[j] * 8);
        cp_async16(smem_u + (uint32_t)((AW + lrow[j] * LDTW + lch[j] * 4) * 4),
                   Bb + (size_t)lrow[j] * HK + lch[j] * 8);
    }
    asm volatile("cp.async.commit_group;" ::: "memory");

    #pragma unroll 1
    for (int it = 0; it < HNIT; it++) {
        const int cur = it & 1;
        const int nxt = cur ^ 1;

        // All warps finished computing stage nxt's previous contents
        __syncthreads();

        // Fill stage nxt with tile it+1 (overlaps MMAs below)
        if (it + 1 < HNIT) {
            const int k0 = (it + 1) * HBK;
            const uint32_t so = (uint32_t)(nxt * STGW) * 4u;
            #pragma unroll
            for (int j = 0; j < 8; j++) {
                cp_async16(smem_u + so + (uint32_t)((lrow[j] * LDTW + lch[j] * 4) * 4),
                           Ab + (size_t)lrow[j] * HK + k0 + lch[j] * 8);
                cp_async16(smem_u + so + (uint32_t)((AW + lrow[j] * LDTW + lch[j] * 4) * 4),
                           Bb + (size_t)lrow[j] * HK + k0 + lch[j] * 8);
            }
        }
        asm volatile("cp.async.commit_group;" ::: "memory");

        // Complete stage cur's group; then barrier for cross-thread visibility
        asm volatile("cp.async.wait_group 1;" ::: "memory");
        __syncthreads();

        const uint32_t* As = smem + cur * STGW;
        const uint32_t* Bs = As + AW;
        #pragma unroll
        for (int kg = 0; kg < HBK / 16; kg++) {     // 4 k16-steps
            const int kb = kg * 8;                  // word base of k-group
            uint32_t af[4][4];
            #pragma unroll
            for (int mf = 0; mf < 4; mf++) {
                const int rb = warpM * 64 + mf * 16 + g;
                const uint2 lo = *reinterpret_cast<const uint2*>(&As[rb * LDTW + kb + 2 * t4]);
                const uint2 hi = *reinterpret_cast<const uint2*>(&As[(rb + 8) * LDTW + kb + 2 * t4]);
                af[mf][0] = lo.x;
                af[mf][1] = hi.x;
                af[mf][2] = lo.y;
                af[mf][3] = hi.y;
            }
            uint32_t bf[8][2];
            #pragma unroll
            for (int nfr = 0; nfr < 8; nfr++) {
                const int nb = warpN * 64 + nfr * 8 + g;
                const uint2 bb = *reinterpret_cast<const uint2*>(&Bs[nb * LDTW + kb + 2 * t4]);
                bf[nfr][0] = bb.x;
                bf[nfr][1] = bb.y;
            }
            #pragma unroll
            for (int mf = 0; mf < 4; mf++)
                #pragma unroll
                for (int nfr = 0; nfr < 8; nfr++)
                    mma_f16(acc[mf][nfr], af[mf][0], af[mf][1], af[mf][2], af[mf][3],
                            bf[nfr][0], bf[nfr][1]);
        }
    }

    // Epilogue
    const int m0 = blockIdx.y * 128 + warpM * 64;
    const int n0 = blockIdx.x * 128 + warpN * 64;
    if (F16OUT) {
        __half2* C = reinterpret_cast<__half2*>(Cv);
        #pragma unroll
        for (int mf = 0; mf < 4; mf++) {
            const int r0 = m0 + mf * 16 + g;
            #pragma unroll
            for (int nfr = 0; nfr < 8; nfr++) {
                const int c0 = n0 + nfr * 8 + t4 * 2;   // even
                C[((size_t)r0 * N + c0) >> 1] =
                    __floats2half2_rn(acc[mf][nfr][0], acc[mf][nfr][1]);
                C[((size_t)(r0 + 8) * N + c0) >> 1] =
                    __floats2half2_rn(acc[mf][nfr][2], acc[mf][nfr][3]);
            }
        }
    } else {
        float* C = reinterpret_cast<float*>(Cv);
        #pragma unroll
        for (int mf = 0; mf < 4; mf++) {
            const int r0 = m0 + mf * 16 + g;
            #pragma unroll
            for (int nfr = 0; nfr < 8; nfr++) {
                const int c0 = n0 + nfr * 8 + t4 * 2;
                *reinterpret_cast<float2*>(C + (size_t)r0 * N + c0) =
                    make_float2(acc[mf][nfr][0], acc[mf][nfr][1]);
                *reinterpret_cast<float2*>(C + (size_t)(r0 + 8) * N + c0) =
                    make_float2(acc[mf][nfr][2], acc[mf][nfr][3]);
            }
        }
    }
}

// ---------------------------------------------------------------------------
// Attention: one block per (n, h); 16-frame causal attention with RoPE.
// Reads fp16 qkv (natural layout); writes fp16 pair-permuted attn output.
// ---------------------------------------------------------------------------
__global__ void __launch_bounds__(64) attn_kernel()
{
    const int nh = blockIdx.x;
    const int n  = nh >> 4;
    const int h  = nh & 15;
    const int b  = n >> 10;
    const int s  = n & 1023;
    const int d  = threadIdx.x;

    __shared__ float qs[FRAMES][HDIM + 1];
    __shared__ float ks[FRAMES][HDIM + 1];
    __shared__ float vs[FRAMES][HDIM];
    __shared__ float ssm[FRAMES][FRAMES];

    const int col = h * HDIM + d;
    #pragma unroll
    for (int t = 0; t < FRAMES; t++) {
        const size_t row = (size_t)((b * FRAMES + t) * SPATIAL + s) * QKV_N;
        qs[t][d] = __half2float(g_qkv_h[row + col]);
        ks[t][d] = __half2float(g_qkv_h[row + HIDDEN + col]);
        vs[t][d] = __half2float(g_qkv_h[row + 2 * HIDDEN + col]);
    }
    __syncthreads();

    const int i = d & 31;
    const float inv_freq = expf(-(float)(2 * i) * (9.210340371976184f / 64.0f));
    float qr[FRAMES], kr[FRAMES];
    #pragma unroll
    for (int t = 0; t < FRAMES; t++) {
        const float fr = (float)t * inv_freq;
        const float c  = cosf(fr);
        const float sn = sinf(fr);
        const float rotq = (d < 32) ? -qs[t][d + 32] : qs[t][d - 32];
        const float rotk = (d < 32) ? -ks[t][d + 32] : ks[t][d - 32];
        qr[t] = qs[t][d] * c + rotq * sn;
        kr[t] = ks[t][d] * c + rotk * sn;
    }
    __syncthreads();
    #pragma unroll
    for (int t = 0; t < FRAMES; t++) { qs[t][d] = qr[t]; ks[t][d] = kr[t]; }
    __syncthreads();

    #pragma unroll
    for (int idx = d; idx < FRAMES * FRAMES; idx += 64) {
        const int tq = idx >> 4;
        const int tk = idx & 15;
        float a;
        if (tk <= tq) {
            a = 0.f;
            #pragma unroll
            for (int e = 0; e < HDIM; e++) a += qs[tq][e] * ks[tk][e];
            a *= 0.125f;
        } else {
            a = -INFINITY;
        }
        ssm[tq][tk] = a;
    }
    __syncthreads();

    if (d < FRAMES) {
        float m = ssm[d][0];
        for (int k = 1; k <= d; k++) m = fmaxf(m, ssm[d][k]);
        float sum = 0.f;
        for (int k = 0; k <= d; k++) {
            const float e = expf(ssm[d][k] - m);
            ssm[d][k] = e;
            sum += e;
        }
        const float r = 1.0f / sum;
        for (int k = 0; k <= d; k++) ssm[d][k] *= r;
        for (int k = d + 1; k < FRAMES; k++) ssm[d][k] = 0.f;
    }
    __syncthreads();

    // Permuted fp16 destination: element index within head = pair-permuted d
    const int g16  = d >> 4;
    const int pl   = (d >> 1) & 7;
    const int dp   = h * HDIM + g16 * 16 + pslot(pl) * 2 + (d & 1);
    #pragma unroll
    for (int t = 0; t < FRAMES; t++) {
        float a = 0.f;
        #pragma unroll
        for (int k = 0; k < FRAMES; k++) a += ssm[t][k] * vs[k][d];
        g_attn_h[(size_t)((b * FRAMES + t) * SPATIAL + s) * HIDDEN + dp] = __float2half_rn(a);
    }
}

// ---------------------------------------------------------------------------
// Launch
// ---------------------------------------------------------------------------
extern "C" void kernel_launch(void* const* d_in, const int* in_sizes, int n_in,
                              void* d_out, int out_size)
{
    const float* x      = (const float*)d_in[0];
    const float* w_qkv  = (const float*)d_in[1];
    const float* w_out  = (const float*)d_in[2];
    const float* gamma  = (const float*)d_in[3];
    const float* beta   = (const float*)d_in[4];

    __half* xn_p;   cudaGetSymbolAddress((void**)&xn_p,   g_xn_h);
    __half* qkv_p;  cudaGetSymbolAddress((void**)&qkv_p,  g_qkv_h);
    __half* attn_p; cudaGetSymbolAddress((void**)&attn_p, g_attn_h);
    __half* wqkv_p; cudaGetSymbolAddress((void**)&wqkv_p, g_wqkv_h);
    __half* wout_p; cudaGetSymbolAddress((void**)&wout_p, g_wout_h);

    cudaFuncSetAttribute(gemm_h<true>,  cudaFuncAttributeMaxDynamicSharedMemorySize,
                         GEMM_SMEM_BYTES);
    cudaFuncSetAttribute(gemm_h<false>, cudaFuncAttributeMaxDynamicSharedMemorySize,
                         GEMM_SMEM_BYTES);

    // 0) Round+permute weights to fp16 (tiny)
    round_perm_w_h<<<QKV_N, 256>>>(w_qkv, (__half2*)wqkv_p);
    round_perm_w_h<<<HIDDEN, 256>>>(w_out, (__half2*)wout_p);

    // 1) LayerNorm -> fp16 permuted
    ln_kernel<<<NTOK, 256>>>(x, gamma, beta);

    // 2) QKV projection [fp16 m16n8k16 mma] -> fp16 qkv (halved C traffic)
    gemm_h<true><<<dim3(QKV_N / 128, NTOK / 128), 128, GEMM_SMEM_BYTES>>>(
        xn_p, wqkv_p, qkv_p, QKV_N);

    // 3) Attention (RoPE + causal softmax + PV) -> fp16 permuted
    attn_kernel<<<NTOK, 64>>>();

    // 4) Output projection -> d_out (fp32)
    gemm_h<false><<<dim3(HIDDEN / 128, NTOK / 128), 128, GEMM_SMEM_BYTES>>>(
        attn_p, wout_p, d_out, HIDDEN);
}